// round 8
// baseline (speedup 1.0000x reference)
#include <cuda_runtime.h>
#include <math.h>

#define DD 160
#define SL 740        // hess slice: 20 rows * 37 stride
#define CSL (36*40)   // conv slice: 36 rows * 40 stride

// Scratch for conv output y [B=2, 160,160,160]
static __device__ float g_y[2 * DD * DD * DD];

static __device__ __forceinline__ int clampi(int v) {
    return min(DD - 1, max(0, v));
}

// ---------------------------------------------------------------------------
// Pass 1: z-marching 3D conv 5x5x5, replicate padding, scalar FFMA.
// Block 128 thr (4tx x 32ty). Tile 32x x 32y, chunk 10 z (+4 warmup).
// Rolling acc[5][8]; 2-slot smem ring; static warmup/tail bounds (exact FMA).
// ---------------------------------------------------------------------------
__global__ __launch_bounds__(128) void conv3d_kernel(
    const float* __restrict__ x, const float* __restrict__ w)
{
    __shared__ float s[2 * CSL];      // 11.5 KB
    __shared__ float wsp[25 * 8];     // weight rows padded to stride 8

    const int tx  = threadIdx.x;      // 0..3 (x group of 8)
    const int ty  = threadIdx.y;      // 0..31
    const int tid = ty * 4 + tx;

    const int bx0 = blockIdx.x * 32;
    const int by0 = blockIdx.y * 32;
    const int b   = blockIdx.z >> 4;
    const int z0  = (blockIdx.z & 15) * 10;

    const float* xb = x + (size_t)b * DD * DD * DD;
    float* yb = g_y + (size_t)b * DD * DD * DD;

    if (tid < 125) wsp[(tid / 5) * 8 + tid % 5] = w[tid];

    // Load table: 1296 slice elems / 128 thr; k=0..9 always valid, k=10 if tid<16
    int lsm[11], lgm[11];
#pragma unroll
    for (int k = 0; k < 11; k++) {
        int idx = tid + k * 128;
        if (idx < 1296) {
            int sy = idx / 36, sx = idx - sy * 36;
            lsm[k] = sy * 40 + sx;
            lgm[k] = clampi(by0 + sy - 2) * DD + clampi(bx0 + sx - 2);
        } else { lsm[k] = 0; lgm[k] = 0; }
    }
    const bool hasK10 = (tid < 16);

    float acc[5][8];
#pragma unroll
    for (int g = 0; g < 5; g++)
#pragma unroll
        for (int o = 0; o < 8; o++) acc[g][o] = 0.f;

    const int xoff = tx * 8;
    const int rowbase = ty * 40 + xoff;

    auto load_slice = [&](int i) {
        float* snew = s + (i & 1) * CSL;
        const float* base = xb + (size_t)clampi(z0 - 2 + i) * (DD * DD);
#pragma unroll
        for (int k = 0; k < 10; k++)
            snew[lsm[k]] = __ldg(base + lgm[k]);
        if (hasK10) snew[lsm[10]] = __ldg(base + lgm[10]);
    };

    auto fma_gens = [&](int i, int gmin, int gmax) {
#pragma unroll
        for (int dy = 0; dy < 5; dy++) {
            const float* row = s + (i & 1) * CSL + rowbase + dy * 40;
            float4 ra = *(const float4*)(row);
            float4 rb = *(const float4*)(row + 4);
            float4 rc = *(const float4*)(row + 8);
            float r[12] = {ra.x, ra.y, ra.z, ra.w, rb.x, rb.y, rb.z, rb.w,
                           rc.x, rc.y, rc.z, rc.w};
#pragma unroll
            for (int g = 0; g < 5; g++) {
                if (g >= gmin && g < gmax) {
                    const float* wr = wsp + ((4 - g) * 5 + dy) * 8;
                    float4 wv = *(const float4*)wr;
                    float w4 = wr[4];
#pragma unroll
                    for (int o = 0; o < 8; o++) {
                        float a = acc[g][o];
                        a = fmaf(wv.x, r[o + 0], a);
                        a = fmaf(wv.y, r[o + 1], a);
                        a = fmaf(wv.z, r[o + 2], a);
                        a = fmaf(wv.w, r[o + 3], a);
                        a = fmaf(w4,   r[o + 4], a);
                        acc[g][o] = a;
                    }
                }
            }
        }
    };

    auto shift = [&]() {
#pragma unroll
        for (int g = 0; g < 4; g++)
#pragma unroll
            for (int o = 0; o < 8; o++) acc[g][o] = acc[g + 1][o];
#pragma unroll
        for (int o = 0; o < 8; o++) acc[4][o] = 0.f;
    };

    auto store_out = [&](int z) {
        float* orow = yb + (((size_t)z * DD) + (by0 + ty)) * DD + bx0 + xoff;
        float4 v0 = {acc[0][0], acc[0][1], acc[0][2], acc[0][3]};
        float4 v1 = {acc[0][4], acc[0][5], acc[0][6], acc[0][7]};
        ((float4*)orow)[0] = v0;
        ((float4*)orow)[1] = v1;
    };

#pragma unroll
    for (int i = 0; i < 4; i++) {
        load_slice(i);
        __syncthreads();
        fma_gens(i, 4 - i, 5);
        shift();
    }
#pragma unroll 1
    for (int i = 4; i < 10; i++) {
        load_slice(i);
        __syncthreads();
        fma_gens(i, 0, 5);
        store_out(z0 - 4 + i);
        shift();
    }
#pragma unroll
    for (int i = 10; i < 14; i++) {
        load_slice(i);
        __syncthreads();
        fma_gens(i, 0, 14 - i);
        store_out(z0 - 4 + i);
        shift();
    }
}

// ---------------------------------------------------------------------------
// Pass 2: z-marching Hessian + MLP. 5-slot rotating smem ring, forced
// 8 blocks/SM (64-reg cap) for occupancy.
// ---------------------------------------------------------------------------
__global__ __launch_bounds__(128, 8) void hess_mlp_kernel(
    const float* __restrict__ w1, const float* __restrict__ b1,
    const float* __restrict__ w2, const float* __restrict__ b2,
    float* __restrict__ out)
{
    __shared__ float s[5 * SL];       // 14.8 KB
    __shared__ float sw1[60], sb1[10], sw2[10], sb2s[1];

    const int tx  = threadIdx.x;   // 0..31
    const int tyq = threadIdx.y;   // 0..3 (warp id)
    const int tid = tyq * 32 + tx;

    const int bx0 = blockIdx.x * 32;
    const int by0 = blockIdx.y * 16;
    const int b   = blockIdx.z >> 4;
    const int z0  = (blockIdx.z & 15) * 10;

    const float* yb = g_y + (size_t)b * DD * DD * DD;

    if (tid < 60)       sw1[tid] = w1[tid];
    else if (tid < 70)  sb1[tid - 60] = b1[tid - 60];
    else if (tid < 80)  sw2[tid - 70] = w2[tid - 70];
    else if (tid == 80) sb2s[0] = b2[0];

    // 720 slice elems / 128 thr; k=0..4 always valid, k=5 if tid<80
    int lsm[6], lgm[6];
#pragma unroll
    for (int k = 0; k < 6; k++) {
        int idx = tid + k * 128;
        if (idx < 720) {
            int sy = idx / 36, sx = idx - sy * 36;
            lsm[k] = sy * 37 + sx;
            lgm[k] = clampi(by0 + sy - 2) * DD + clampi(bx0 + sx - 2);
        } else { lsm[k] = 0; lgm[k] = 0; }
    }
    const bool hasK5 = (tid < 80);

    const bool bxL = (bx0 == 0), bxR = (bx0 + 32 == DD);
    const bool byL = (by0 == 0), byR = (by0 + 16 == DD);
    const bool edge = bxL | bxR | byL | byR;

    auto load_slice = [&](int gz, float* dst) {
        if ((unsigned)gz < DD) {
            const float* base = yb + (size_t)gz * (DD * DD);
#pragma unroll
            for (int k = 0; k < 5; k++)
                dst[lsm[k]] = __ldg(base + lgm[k]);
            if (hasK5) dst[lsm[5]] = __ldg(base + lgm[5]);
        } else {
            int e; const float *p0, *p1;
            if (gz < 0) { e = -gz; p0 = yb; p1 = yb + DD * DD; }
            else        { e = gz - (DD - 1);
                          p0 = yb + (size_t)(DD - 1) * DD * DD;
                          p1 = yb + (size_t)(DD - 2) * DD * DD; }
            float w0 = 1.f + (float)e, w1n = -(float)e;
#pragma unroll
            for (int k = 0; k < 5; k++)
                dst[lsm[k]] = w0 * __ldg(p0 + lgm[k]) + w1n * __ldg(p1 + lgm[k]);
            if (hasK5)
                dst[lsm[5]] = w0 * __ldg(p0 + lgm[5]) + w1n * __ldg(p1 + lgm[5]);
        }
    };

    auto fixup = [&](float* sl) {
        if (bxL | bxR) {
            if (tx < 20) {
                float* row = sl + tx * 37;
                if (bxL) { float a = row[2],  c2 = row[3];
                           row[1]  = 2.f * a - c2; row[0]  = 3.f * a - 2.f * c2; }
                if (bxR) { float a = row[33], c2 = row[32];
                           row[34] = 2.f * a - c2; row[35] = 3.f * a - 2.f * c2; }
            }
            __syncwarp();
        }
        if (byL | byR) {
            for (int xx = tx; xx < 36; xx += 32) {
                float* p = sl + xx;
                if (byL) { float a = p[2 * 37],  c2 = p[3 * 37];
                           p[37]      = 2.f * a - c2; p[0]       = 3.f * a - 2.f * c2; }
                if (byR) { float a = p[17 * 37], c2 = p[16 * 37];
                           p[18 * 37] = 2.f * a - c2; p[19 * 37] = 3.f * a - 2.f * c2; }
            }
        }
    };

    // Rotating slot pointers: sl0..sl4 hold slices z-2..z+2
    int sl0 = 0, sl1 = SL, sl2 = 2 * SL, sl3 = 3 * SL, sl4 = 4 * SL;

    load_slice(z0 - 2, s + sl0);
    load_slice(z0 - 1, s + sl1);
    load_slice(z0,     s + sl2);
    load_slice(z0 + 1, s + sl3);
    __syncthreads();
    if (edge) {
        if (tid < 32) {
            fixup(s + sl0); fixup(s + sl1); fixup(s + sl2); fixup(s + sl3);
        }
        __syncthreads();
    }

    const int gx = bx0 + tx;
    const float fxc = (gx == 0 || gx == DD - 1) ? 2.f : 1.f;
    const int y4 = tyq * 4;
    const int coff = (y4 + 2) * 37 + tx + 2;

    for (int z = z0; z < z0 + 10; z++) {
        load_slice(z + 2, s + sl4);
        __syncthreads();
        if (edge) {
            if (tid < 32) fixup(s + sl4);
            __syncthreads();
        }

        const float* sm2 = s + sl0;
        const float* sm1 = s + sl1;
        const float* sc  = s + sl2;
        const float* sp1 = s + sl3;
        const float* sp2 = s + sl4;
        const float fz = (z == 0 || z == DD - 1) ? 2.f : 1.f;

        float h[4][6];
#pragma unroll
        for (int v = 0; v < 4; v++) {
            const int c = coff + v * 37;
            const int gy = by0 + y4 + v;
            const float fy = (gy == 0 || gy == DD - 1) ? 2.f : 1.f;
            float cc = sc[c];
            h[v][0] = fz * 0.25f * (sp2[c] - 2.f * cc + sm2[c]);
            h[v][1] = 0.25f * (sp1[c + 37] - sp1[c - 37] - sm1[c + 37] + sm1[c - 37]);
            h[v][2] = 0.25f * (sp1[c + 1] - sp1[c - 1] - sm1[c + 1] + sm1[c - 1]);
            h[v][3] = fy * 0.25f * (sc[c + 74] - 2.f * cc + sc[c - 74]);
            h[v][4] = 0.25f * (sc[c + 38] - sc[c + 36] - sc[c - 36] + sc[c - 38]);
            h[v][5] = fxc * 0.25f * (sc[c + 2] - 2.f * cc + sc[c - 2]);
        }

        float a2[4];
#pragma unroll
        for (int v = 0; v < 4; v++) a2[v] = sb2s[0];

#pragma unroll
        for (int o = 0; o < 10; o++) {
            float wr0 = sw1[o * 6 + 0], wr1 = sw1[o * 6 + 1], wr2 = sw1[o * 6 + 2];
            float wr3 = sw1[o * 6 + 3], wr4 = sw1[o * 6 + 4], wr5 = sw1[o * 6 + 5];
            const float bo  = sb1[o];
            const float w2o = sw2[o];
#pragma unroll
            for (int v = 0; v < 4; v++) {
                float t = bo;
                t = fmaf(wr0, h[v][0], t);
                t = fmaf(wr1, h[v][1], t);
                t = fmaf(wr2, h[v][2], t);
                t = fmaf(wr3, h[v][3], t);
                t = fmaf(wr4, h[v][4], t);
                t = fmaf(wr5, h[v][5], t);
                a2[v] = fmaf(w2o, fmaxf(t, 0.f), a2[v]);
            }
        }

#pragma unroll
        for (int v = 0; v < 4; v++) {
            float sg = 1.f / (1.f + __expf(-a2[v]));
            out[(((size_t)b * DD + z) * DD + (by0 + y4 + v)) * DD + gx] = sg;
        }

        // rotate ring: oldest slot becomes the new load target
        int t0 = sl0;
        sl0 = sl1; sl1 = sl2; sl2 = sl3; sl3 = sl4; sl4 = t0;
    }
}

// ---------------------------------------------------------------------------
// Launch: inputs per metadata order: x, conv_w, w1, b1, w2, b2
// ---------------------------------------------------------------------------
extern "C" void kernel_launch(void* const* d_in, const int* in_sizes, int n_in,
                              void* d_out, int out_size)
{
    const float* x  = (const float*)d_in[0];
    const float* cw = (const float*)d_in[1];
    const float* w1 = (const float*)d_in[2];
    const float* b1 = (const float*)d_in[3];
    const float* w2 = (const float*)d_in[4];
    const float* b2 = (const float*)d_in[5];
    float* out = (float*)d_out;

    conv3d_kernel<<<dim3(5, 5, 32), dim3(4, 32, 1)>>>(x, cw);
    hess_mlp_kernel<<<dim3(5, 10, 32), dim3(32, 4, 1)>>>(w1, b1, w2, b2, out);
}